// round 2
// baseline (speedup 1.0000x reference)
#include <cuda_runtime.h>

#define DIM_TOTAL 1920

// Segmented linear: y[n,v,i] = scale * sum_u x[n, XOFF + u*D + i] * W[woff + u*MUL + v]
// Formulated as a GEMM over (n rows) x (v cols) with D-vector elements, so the
// irrep interleave stays contiguous for every global load/store (float4).
template<int D, int BM, int BN, int BK, int TM, int TN, int XOFF, int MUL>
__global__ __launch_bounds__((BM/TM)*(BN/TN))
void seg_linear(const float* __restrict__ x, const float* __restrict__ w,
                float* __restrict__ out, int woff, float scale)
{
    constexpr int THREADS = (BM/TM)*(BN/TN);
    constexpr int NTX     = BN/TN;
    constexpr int ROWF4   = BK*D/4;   // float4s per A row per tile
    constexpr int BROWF4  = BN/4;     // float4s per B row

    static_assert((BK*D) % 4 == 0, "A row must be float4-able");
    static_assert((TM*D) % 4 == 0, "a frag must be float4-able");
    static_assert(TN == 4, "b frag is one float4");
    static_assert((BM*ROWF4) % THREADS == 0, "A tile load must divide evenly");
    static_assert((BK*BROWF4) % THREADS == 0, "B tile load must divide evenly");

    __shared__ float As[BK][BM*D];
    __shared__ float Bs[BK][BN];

    const int n0  = blockIdx.x * BM;
    const int v0  = blockIdx.y * BN;
    const int tid = threadIdx.x;
    const int tx  = tid % NTX;
    const int ty  = tid / NTX;

    float acc[TM][TN*D];
    #pragma unroll
    for (int tm = 0; tm < TM; ++tm)
        #pragma unroll
        for (int t = 0; t < TN*D; ++t)
            acc[tm][t] = 0.0f;

    for (int kt = 0; kt < MUL/BK; ++kt) {
        // ---- load A tile: BM rows x BK*D contiguous floats each ----
        #pragma unroll
        for (int it = 0; it < (BM*ROWF4)/THREADS; ++it) {
            int idx = tid + it*THREADS;
            int m   = idx / ROWF4;
            int c4  = idx - m*ROWF4;
            const float4 vv = *reinterpret_cast<const float4*>(
                x + (n0 + m)*DIM_TOTAL + XOFF + kt*(BK*D) + c4*4);
            int t = c4*4;
            As[(t+0)/D][m*D + (t+0)%D] = vv.x;
            As[(t+1)/D][m*D + (t+1)%D] = vv.y;
            As[(t+2)/D][m*D + (t+2)%D] = vv.z;
            As[(t+3)/D][m*D + (t+3)%D] = vv.w;
        }
        // ---- load B tile: W[u, v] row-major ----
        #pragma unroll
        for (int it = 0; it < (BK*BROWF4)/THREADS; ++it) {
            int idx = tid + it*THREADS;
            int r   = idx / BROWF4;
            int c   = idx - r*BROWF4;
            *reinterpret_cast<float4*>(&Bs[r][c*4]) =
                *reinterpret_cast<const float4*>(w + woff + (kt*BK + r)*MUL + v0 + c*4);
        }
        __syncthreads();

        #pragma unroll
        for (int k = 0; k < BK; ++k) {
            float a[TM*D];
            #pragma unroll
            for (int q = 0; q < (TM*D)/4; ++q)
                *reinterpret_cast<float4*>(&a[q*4]) =
                    *reinterpret_cast<const float4*>(&As[k][ty*TM*D + q*4]);
            float b[TN];
            *reinterpret_cast<float4*>(&b[0]) =
                *reinterpret_cast<const float4*>(&Bs[k][tx*TN]);
            #pragma unroll
            for (int tm = 0; tm < TM; ++tm)
                #pragma unroll
                for (int tn = 0; tn < TN; ++tn)
                    #pragma unroll
                    for (int i = 0; i < D; ++i)
                        acc[tm][tn*D + i] += a[tm*D + i] * b[tn];
        }
        __syncthreads();
    }

    // ---- epilogue: scale + contiguous float4 stores ----
    #pragma unroll
    for (int tm = 0; tm < TM; ++tm) {
        float* op = out + (n0 + ty*TM + tm)*DIM_TOTAL + XOFF + (v0 + tx*TN)*D;
        #pragma unroll
        for (int q = 0; q < (TN*D)/4; ++q) {
            float4 vv;
            vv.x = acc[tm][q*4 + 0] * scale;
            vv.y = acc[tm][q*4 + 1] * scale;
            vv.z = acc[tm][q*4 + 2] * scale;
            vv.w = acc[tm][q*4 + 3] * scale;
            *reinterpret_cast<float4*>(op + q*4) = vv;
        }
    }
}

extern "C" void kernel_launch(void* const* d_in, const int* in_sizes, int n_in,
                              void* d_out, int out_size)
{
    const float* x   = (const float*)d_in[0];
    const float* w   = (const float*)d_in[1];
    float*       out = (float*)d_out;
    (void)in_sizes; (void)n_in; (void)out_size;

    // seg0: mul=512, d=1, xoff=0,    woff=0
    {
        dim3 grid(16384/128, 512/64);
        seg_linear<1,128,64,16,8,4,0,512><<<grid, 256>>>(
            x, w, out, 0, 0.044194173824159216f /* 1/sqrt(512) */);
    }
    // seg1: mul=256, d=3, xoff=512,  woff=512*512
    {
        dim3 grid(16384/64, 256/64);
        seg_linear<3,64,64,16,4,4,512,256><<<grid, 256>>>(
            x, w, out, 512*512, 0.0625f /* 1/sqrt(256) */);
    }
    // seg2: mul=128, d=5, xoff=1280, woff=512*512+256*256
    {
        dim3 grid(16384/64, 128/64);
        seg_linear<5,64,64,16,4,4,1280,128><<<grid, 256>>>(
            x, w, out, 512*512 + 256*256, 0.08838834764831843f /* 1/sqrt(128) */);
    }
}

// round 3
// speedup vs baseline: 1.9802x; 1.9802x over previous
#include <cuda_runtime.h>
#include <cstdint>

#define DIM_TOTAL 1920

__device__ __forceinline__ uint32_t f2tf32(float f) {
    uint32_t u;
    asm("cvt.rna.tf32.f32 %0, %1;" : "=r"(u) : "f"(f));
    return u;
}

// Segmented linear as tensor-core GEMM.
// Rows r = n*D + i (component-expanded tokens), K dim = input channel u,
// cols = output channel v.  A'[r][u] = x[n, XOFF + u*D + i],
// out[n, XOFF + v*D + i] = scale * sum_u A'[n*D+i][u] * W[u][v].
template<int D, int BM, int BN, int BK, int WM, int WN, int XOFF, int MUL>
__global__ __launch_bounds__((BM/WM)*(BN/WN)*32)
void seg_linear_tc(const float* __restrict__ x, const float* __restrict__ w,
                   float* __restrict__ out, int woff, float scale)
{
    constexpr int THREADS  = (BM/WM)*(BN/WN)*32;
    constexpr int AS       = BK + 4;     // As row stride (conflict-free frag loads)
    constexpr int BS       = BN + 8;     // Bs row stride (conflict-free frag loads)
    constexpr int MT       = WM/16, NT = WN/8;
    constexpr int KT       = MUL/BK;
    constexpr int NPB      = BM/D;       // tokens per block
    constexpr int CPN      = BK*D/4;     // float4s per token per k-chunk
    constexpr int A_F4_TOT = BM*BK/4;
    constexpr int B_F4_TOT = BK*BN/4;
    constexpr int A_IT     = (A_F4_TOT + THREADS - 1)/THREADS;
    constexpr int B_IT     = (B_F4_TOT + THREADS - 1)/THREADS;
    constexpr int WARPS_N  = BN/WN;

    static_assert(BM % D == 0, "whole tokens per block");
    static_assert(A_F4_TOT % THREADS == 0, "A tile divides");
    static_assert((BM*BN/4) % THREADS == 0, "epilogue divides");

    __shared__ union {
        struct { float a[BM][AS]; float b[BK][BS]; } ab;
        float c[BM][BN];
    } sm;

    const int tid  = threadIdx.x;
    const int warp = tid >> 5;
    const int lane = tid & 31;
    const int g    = lane >> 2;   // group id 0..7
    const int q    = lane & 3;    // tid in group 0..3
    const int wy   = warp / WARPS_N;
    const int wx   = warp % WARPS_N;

    const int n0g = blockIdx.x * NPB;
    const int v0  = blockIdx.y * BN;

    float acc[MT][NT][4];
    #pragma unroll
    for (int mt = 0; mt < MT; ++mt)
        #pragma unroll
        for (int nt = 0; nt < NT; ++nt)
            #pragma unroll
            for (int e = 0; e < 4; ++e)
                acc[mt][nt][e] = 0.0f;

    float4 aR[A_IT], bR[B_IT];

    auto loadT = [&](int kt) {
        #pragma unroll
        for (int it = 0; it < A_IT; ++it) {
            int idx = tid + it*THREADS;
            int nl = idx / CPN, c4 = idx % CPN;
            aR[it] = *reinterpret_cast<const float4*>(
                x + (n0g + nl)*DIM_TOTAL + XOFF + kt*(BK*D) + c4*4);
        }
        #pragma unroll
        for (int it = 0; it < B_IT; ++it) {
            int idx = tid + it*THREADS;
            if (B_F4_TOT % THREADS == 0 || idx < B_F4_TOT) {
                int r = idx / (BN/4), c4 = idx % (BN/4);
                bR[it] = *reinterpret_cast<const float4*>(
                    w + woff + (kt*BK + r)*MUL + v0 + c4*4);
            }
        }
    };

    auto storeT = [&]() {
        #pragma unroll
        for (int it = 0; it < A_IT; ++it) {
            int idx = tid + it*THREADS;
            int nl = idx / CPN, c4 = idx % CPN;
            int t = c4*4;
            float v[4] = {aR[it].x, aR[it].y, aR[it].z, aR[it].w};
            #pragma unroll
            for (int e = 0; e < 4; ++e)
                sm.ab.a[nl*D + (t+e)%D][(t+e)/D] = __uint_as_float(f2tf32(v[e]));
        }
        #pragma unroll
        for (int it = 0; it < B_IT; ++it) {
            int idx = tid + it*THREADS;
            if (B_F4_TOT % THREADS == 0 || idx < B_F4_TOT) {
                int r = idx / (BN/4), c4 = idx % (BN/4);
                sm.ab.b[r][c4*4 + 0] = __uint_as_float(f2tf32(bR[it].x));
                sm.ab.b[r][c4*4 + 1] = __uint_as_float(f2tf32(bR[it].y));
                sm.ab.b[r][c4*4 + 2] = __uint_as_float(f2tf32(bR[it].z));
                sm.ab.b[r][c4*4 + 3] = __uint_as_float(f2tf32(bR[it].w));
            }
        }
    };

    auto compute = [&]() {
        #pragma unroll
        for (int kk = 0; kk < BK/8; ++kk) {
            uint32_t a[MT][4];
            #pragma unroll
            for (int mt = 0; mt < MT; ++mt) {
                int r = wy*WM + mt*16 + g;
                a[mt][0] = __float_as_uint(sm.ab.a[r    ][kk*8 + q    ]);
                a[mt][1] = __float_as_uint(sm.ab.a[r + 8][kk*8 + q    ]);
                a[mt][2] = __float_as_uint(sm.ab.a[r    ][kk*8 + q + 4]);
                a[mt][3] = __float_as_uint(sm.ab.a[r + 8][kk*8 + q + 4]);
            }
            uint32_t b[NT][2];
            #pragma unroll
            for (int nt = 0; nt < NT; ++nt) {
                int col = wx*WN + nt*8 + g;
                b[nt][0] = __float_as_uint(sm.ab.b[kk*8 + q    ][col]);
                b[nt][1] = __float_as_uint(sm.ab.b[kk*8 + q + 4][col]);
            }
            #pragma unroll
            for (int mt = 0; mt < MT; ++mt)
                #pragma unroll
                for (int nt = 0; nt < NT; ++nt)
                    asm volatile(
                        "mma.sync.aligned.m16n8k8.row.col.f32.tf32.tf32.f32 "
                        "{%0,%1,%2,%3}, {%4,%5,%6,%7}, {%8,%9}, {%0,%1,%2,%3};"
                        : "+f"(acc[mt][nt][0]), "+f"(acc[mt][nt][1]),
                          "+f"(acc[mt][nt][2]), "+f"(acc[mt][nt][3])
                        : "r"(a[mt][0]), "r"(a[mt][1]), "r"(a[mt][2]), "r"(a[mt][3]),
                          "r"(b[nt][0]), "r"(b[nt][1]));
        }
    };

    // ---- pipelined mainloop: register prefetch of next tile ----
    loadT(0);
    storeT();
    __syncthreads();
    for (int kt = 1; kt < KT; ++kt) {
        loadT(kt);
        compute();
        __syncthreads();
        storeT();
        __syncthreads();
    }
    compute();

    // ---- epilogue: stage C in smem, then contiguous float4 stores ----
    __syncthreads();
    #pragma unroll
    for (int mt = 0; mt < MT; ++mt)
        #pragma unroll
        for (int nt = 0; nt < NT; ++nt) {
            int r   = wy*WM + mt*16 + g;
            int col = wx*WN + nt*8 + 2*q;
            sm.c[r    ][col    ] = acc[mt][nt][0];
            sm.c[r    ][col + 1] = acc[mt][nt][1];
            sm.c[r + 8][col    ] = acc[mt][nt][2];
            sm.c[r + 8][col + 1] = acc[mt][nt][3];
        }
    __syncthreads();

    constexpr int TOT4 = BM*BN/4;
    #pragma unroll
    for (int it = 0; it < TOT4/THREADS; ++it) {
        int f    = tid + it*THREADS;
        int base = f*4;
        int nl   = base / (BN*D);
        int j    = base % (BN*D);
        float4 vv;
        vv.x = sm.c[nl*D + (j+0)%D][(j+0)/D] * scale;
        vv.y = sm.c[nl*D + (j+1)%D][(j+1)/D] * scale;
        vv.z = sm.c[nl*D + (j+2)%D][(j+2)/D] * scale;
        vv.w = sm.c[nl*D + (j+3)%D][(j+3)/D] * scale;
        *reinterpret_cast<float4*>(
            out + (n0g + nl)*DIM_TOTAL + XOFF + v0*D + j) = vv;
    }
}

extern "C" void kernel_launch(void* const* d_in, const int* in_sizes, int n_in,
                              void* d_out, int out_size)
{
    const float* x   = (const float*)d_in[0];
    const float* w   = (const float*)d_in[1];
    float*       out = (float*)d_out;
    (void)in_sizes; (void)n_in; (void)out_size;

    // seg0: mul=512, d=1  (16384 rows x 512 cols, K=512)
    {
        dim3 grid(16384/128, 512/64);
        seg_linear_tc<1,128,64,32,32,32,0,512><<<grid, 256>>>(
            x, w, out, 0, 0.044194173824159216f);
    }
    // seg1: mul=256, d=3  (49152 rows x 256 cols, K=256)
    {
        dim3 grid(49152/96, 256/64);
        seg_linear_tc<3,96,64,32,32,32,512,256><<<grid, 192>>>(
            x, w, out, 512*512, 0.0625f);
    }
    // seg2: mul=128, d=5  (81920 rows x 128 cols, K=128)
    {
        dim3 grid(81920/80, 128/64);
        seg_linear_tc<5,80,64,32,16,32,1280,128><<<grid, 320>>>(
            x, w, out, 512*512 + 256*256, 0.08838834764831843f);
    }
}

// round 4
// speedup vs baseline: 2.6615x; 1.3440x over previous
#include <cuda_runtime.h>
#include <cstdint>

#define DIM_TOTAL 1920

__device__ __forceinline__ uint32_t f2tf32(float f) {
    uint32_t u;
    asm("cvt.rna.tf32.f32 %0, %1;" : "=r"(u) : "f"(f));
    return u;
}

__device__ __forceinline__ void cp16(float* dst, const float* src) {
    uint32_t d = (uint32_t)__cvta_generic_to_shared(dst);
    asm volatile("cp.async.cg.shared.global [%0], [%1], 16;" :: "r"(d), "l"(src));
}

// Segmented linear as tensor-core GEMM, cp.async 3-stage pipeline.
// Component-expanded rows r = n*D + i; A'[r][u] = x[n, XOFF + u*D + i].
// A staged raw token-major in smem (cp.async-able); de-interleave + tf32 cvt
// happen at fragment load via precomputed per-row offsets.
template<int D, int BM, int BN, int BK, int WM, int WN, int XOFF, int MUL>
__global__ void __launch_bounds__((BM/WM)*(BN/WN)*32, 2)
seg_linear_tc(const float* __restrict__ x, const float* __restrict__ w,
              float* __restrict__ out, int woff, float scale)
{
    constexpr int THREADS = (BM/WM)*(BN/WN)*32;
    constexpr int NPB   = BM/D;          // tokens per block
    constexpr int ATOK  = BK*D + 4;      // smem floats per token per stage (16B-aligned pad)
    constexpr int BSTR  = BN + 8;        // B row stride (conflict-free frag loads)
    constexpr int A_F   = NPB*ATOK;
    constexpr int B_F   = BK*BSTR;
    constexpr int STAGE_F = A_F + B_F;
    constexpr int CPN   = BK*D/4;        // 16B chunks per token per tile
    constexpr int A_CH  = NPB*CPN;
    constexpr int B_CH  = BK*BN/4;
    constexpr int KT    = MUL/BK;
    constexpr int MT    = WM/16, NT = WN/8;
    constexpr int WARPS_N = BN/WN;

    static_assert(BM % D == 0, "whole tokens per block");
    static_assert(A_CH % THREADS == 0 && B_CH % THREADS == 0, "copy divides");
    static_assert((BM*BN/4) % THREADS == 0, "epilogue divides");
    static_assert(KT >= 2, "pipeline needs >=2 tiles");

    extern __shared__ float sm[];

    const int tid  = threadIdx.x;
    const int warp = tid >> 5, lane = tid & 31;
    const int g = lane >> 2, q = lane & 3;
    const int wy = warp / WARPS_N, wx = warp % WARPS_N;
    const int n0g = blockIdx.x * NPB;
    const int v0  = blockIdx.y * BN;

    auto load_stage = [&](int kt, float* st) {
        float* As = st;
        float* Bs = st + A_F;
        #pragma unroll
        for (int it = 0; it < A_CH/THREADS; ++it) {
            int idx = tid + it*THREADS;
            int nl = idx / CPN, c4 = idx - nl*CPN;
            cp16(As + nl*ATOK + c4*4,
                 x + (size_t)(n0g + nl)*DIM_TOTAL + XOFF + kt*(BK*D) + c4*4);
        }
        #pragma unroll
        for (int it = 0; it < B_CH/THREADS; ++it) {
            int idx = tid + it*THREADS;
            int r = idx / (BN/4), c4 = idx - r*(BN/4);
            cp16(Bs + r*BSTR + c4*4,
                 w + woff + (size_t)(kt*BK + r)*MUL + v0 + c4*4);
        }
    };

    float acc[MT][NT][4];
    #pragma unroll
    for (int mt = 0; mt < MT; ++mt)
        #pragma unroll
        for (int nt = 0; nt < NT; ++nt)
            #pragma unroll
            for (int e = 0; e < 4; ++e)
                acc[mt][nt][e] = 0.0f;

    // per-row A offsets (de-interleave hoisted out of the k loop)
    int aOff0[MT], aOff1[MT];
    #pragma unroll
    for (int mt = 0; mt < MT; ++mt) {
        int r0 = wy*WM + mt*16 + g;
        int r1 = r0 + 8;
        aOff0[mt] = (r0/D)*ATOK + (r0 - (r0/D)*D) + q*D;
        aOff1[mt] = (r1/D)*ATOK + (r1 - (r1/D)*D) + q*D;
    }
    int bCol[NT];
    #pragma unroll
    for (int nt = 0; nt < NT; ++nt)
        bCol[nt] = wx*WN + nt*8 + g;

    // ---- prologue: fill 2 stages ----
    load_stage(0, sm);
    asm volatile("cp.async.commit_group;" ::: "memory");
    load_stage(1, sm + STAGE_F);
    asm volatile("cp.async.commit_group;" ::: "memory");

    int sidx = 0;
    for (int kt = 0; kt < KT; ++kt) {
        asm volatile("cp.async.wait_group 1;" ::: "memory");
        __syncthreads();
        if (kt + 2 < KT) {
            int ns = sidx + 2; if (ns >= 3) ns -= 3;
            load_stage(kt + 2, sm + ns*STAGE_F);
        }
        asm volatile("cp.async.commit_group;" ::: "memory");

        const float* As = sm + sidx*STAGE_F;
        const float* Bs = As + A_F;
        #pragma unroll
        for (int kk = 0; kk < BK/8; ++kk) {
            uint32_t a[MT][4];
            #pragma unroll
            for (int mt = 0; mt < MT; ++mt) {
                a[mt][0] = f2tf32(As[aOff0[mt] + (kk*8)*D]);
                a[mt][1] = f2tf32(As[aOff1[mt] + (kk*8)*D]);
                a[mt][2] = f2tf32(As[aOff0[mt] + (kk*8 + 4)*D]);
                a[mt][3] = f2tf32(As[aOff1[mt] + (kk*8 + 4)*D]);
            }
            uint32_t b[NT][2];
            #pragma unroll
            for (int nt = 0; nt < NT; ++nt) {
                b[nt][0] = f2tf32(Bs[(kk*8 + q    )*BSTR + bCol[nt]]);
                b[nt][1] = f2tf32(Bs[(kk*8 + q + 4)*BSTR + bCol[nt]]);
            }
            #pragma unroll
            for (int mt = 0; mt < MT; ++mt)
                #pragma unroll
                for (int nt = 0; nt < NT; ++nt)
                    asm volatile(
                        "mma.sync.aligned.m16n8k8.row.col.f32.tf32.tf32.f32 "
                        "{%0,%1,%2,%3}, {%4,%5,%6,%7}, {%8,%9}, {%0,%1,%2,%3};"
                        : "+f"(acc[mt][nt][0]), "+f"(acc[mt][nt][1]),
                          "+f"(acc[mt][nt][2]), "+f"(acc[mt][nt][3])
                        : "r"(a[mt][0]), "r"(a[mt][1]), "r"(a[mt][2]), "r"(a[mt][3]),
                          "r"(b[nt][0]), "r"(b[nt][1]));
        }
        ++sidx; if (sidx >= 3) sidx = 0;
    }

    // ---- epilogue: stage C in smem (stages dead), contiguous float4 stores ----
    __syncthreads();
    float (*C)[BN] = reinterpret_cast<float (*)[BN]>(sm);
    #pragma unroll
    for (int mt = 0; mt < MT; ++mt)
        #pragma unroll
        for (int nt = 0; nt < NT; ++nt) {
            int r   = wy*WM + mt*16 + g;
            int col = wx*WN + nt*8 + 2*q;
            C[r    ][col    ] = acc[mt][nt][0];
            C[r    ][col + 1] = acc[mt][nt][1];
            C[r + 8][col    ] = acc[mt][nt][2];
            C[r + 8][col + 1] = acc[mt][nt][3];
        }
    __syncthreads();

    constexpr int TOT4 = BM*BN/4;
    #pragma unroll
    for (int it = 0; it < TOT4/THREADS; ++it) {
        int f    = tid + it*THREADS;
        int base = f*4;
        int nl   = base / (BN*D);
        int j    = base - nl*(BN*D);
        float4 vv;
        vv.x = C[nl*D + (j+0)%D][(j+0)/D] * scale;
        vv.y = C[nl*D + (j+1)%D][(j+1)/D] * scale;
        vv.z = C[nl*D + (j+2)%D][(j+2)/D] * scale;
        vv.w = C[nl*D + (j+3)%D][(j+3)/D] * scale;
        *reinterpret_cast<float4*>(
            out + (size_t)(n0g + nl)*DIM_TOTAL + XOFF + v0*D + j) = vv;
    }
}

extern "C" void kernel_launch(void* const* d_in, const int* in_sizes, int n_in,
                              void* d_out, int out_size)
{
    const float* x   = (const float*)d_in[0];
    const float* w   = (const float*)d_in[1];
    float*       out = (float*)d_out;
    (void)in_sizes; (void)n_in; (void)out_size;

    // seg0: D=1, MUL=512: 16384 x 512, K=512. Tile 128x128x32, 8 warps (64x32).
    {
        auto kfn = seg_linear_tc<1,128,128,32,64,32,0,512>;
        constexpr int STAGE_B = (128*(32+4) + 32*(128+8))*4;   // 35840
        constexpr int SMEM = (3*STAGE_B > 128*128*4) ? 3*STAGE_B : 128*128*4; // 107520
        cudaFuncSetAttribute(kfn, cudaFuncAttributeMaxDynamicSharedMemorySize, SMEM);
        dim3 grid(16384/128, 512/128);
        kfn<<<grid, 256, SMEM>>>(x, w, out, 0, 0.044194173824159216f);
    }
    // seg1: D=3, MUL=256: 49152 x 256, K=256. Tile 96x128x32, 8 warps (48x32).
    {
        auto kfn = seg_linear_tc<3,96,128,32,48,32,512,256>;
        constexpr int STAGE_B = (32*(96+4) + 32*(128+8))*4;    // 30208
        constexpr int SMEM = (3*STAGE_B > 96*128*4) ? 3*STAGE_B : 96*128*4;   // 90624
        cudaFuncSetAttribute(kfn, cudaFuncAttributeMaxDynamicSharedMemorySize, SMEM);
        dim3 grid(49152/96, 256/128);
        kfn<<<grid, 256, SMEM>>>(x, w, out, 512*512, 0.0625f);
    }
    // seg2: D=5, MUL=128: 81920 x 128, K=128. Tile 160x128x16, 4 warps (80x64).
    {
        auto kfn = seg_linear_tc<5,160,128,16,80,64,1280,128>;
        constexpr int STAGE_B = (32*(80+4) + 16*(128+8))*4;    // 19456
        constexpr int SMEM = (3*STAGE_B > 160*128*4) ? 3*STAGE_B : 160*128*4; // 81920
        cudaFuncSetAttribute(kfn, cudaFuncAttributeMaxDynamicSharedMemorySize, SMEM);
        dim3 grid(81920/160, 128/128);
        kfn<<<grid, 128, SMEM>>>(x, w, out, 512*512 + 256*256, 0.08838834764831843f);
    }
}

// round 8
// speedup vs baseline: 3.1224x; 1.1732x over previous
#include <cuda_runtime.h>
#include <cstdint>

#define DIM_TOTAL 1920

__device__ __forceinline__ uint32_t f2tf32(float f) {
    uint32_t u;
    asm("cvt.rna.tf32.f32 %0, %1;" : "=r"(u) : "f"(f));
    return u;
}

__device__ __forceinline__ void cp16(float* dst, const float* src) {
    uint32_t d = (uint32_t)__cvta_generic_to_shared(dst);
    asm volatile("cp.async.cg.shared.global [%0], [%1], 16;" :: "r"(d), "l"(src));
}

// Segmented linear as tensor-core GEMM, cp.async 3-stage pipeline.
// Component-expanded rows r = n*D + i; A'[r][u] = x[n, XOFF + u*D + i].
// A fragments are fed RAW fp32 to HMMA.TF32 (hardware truncates to tf32);
// B fragments get cvt.rna (unbiased) at load. Wide 64-col warp tiles keep
// the issue-per-MMA ratio low (schedulers were the round-4 bottleneck).
template<int D, int BM, int BN, int BK, int WM, int WN, int XOFF, int MUL>
__global__ void __launch_bounds__((BM/WM)*(BN/WN)*32, 2)
seg_linear_tc(const float* __restrict__ x, const float* __restrict__ w,
              float* __restrict__ out, int woff, float scale)
{
    constexpr int THREADS = (BM/WM)*(BN/WN)*32;
    constexpr int NPB   = BM/D;          // tokens per block
    constexpr int ATOK  = BK*D + 4;      // smem floats per token per stage
    constexpr int BSTR  = BN + 8;        // B row stride (conflict-free frag loads)
    constexpr int A_F   = NPB*ATOK;
    constexpr int B_F   = BK*BSTR;
    constexpr int STAGE_F = A_F + B_F;
    constexpr int CPN   = BK*D/4;        // 16B chunks per token per tile
    constexpr int A_CH  = NPB*CPN;
    constexpr int B_CH  = BK*BN/4;
    constexpr int KT    = MUL/BK;
    constexpr int MT    = WM/16, NT = WN/8;
    constexpr int WARPS_N = BN/WN;

    static_assert(BM % D == 0, "whole tokens per block");
    static_assert(A_CH % THREADS == 0 && B_CH % THREADS == 0, "copy divides");
    static_assert((BM*BN/4) % THREADS == 0, "epilogue divides");
    static_assert(KT >= 2, "pipeline needs >=2 tiles");

    extern __shared__ float sm[];

    const int tid  = threadIdx.x;
    const int warp = tid >> 5, lane = tid & 31;
    const int g = lane >> 2, q = lane & 3;
    const int wy = warp / WARPS_N, wx = warp % WARPS_N;
    const int n0g = blockIdx.x * NPB;
    const int v0  = blockIdx.y * BN;

    auto load_stage = [&](int kt, float* st) {
        float* As = st;
        float* Bs = st + A_F;
        #pragma unroll
        for (int it = 0; it < A_CH/THREADS; ++it) {
            int idx = tid + it*THREADS;
            int nl = idx / CPN, c4 = idx - nl*CPN;
            cp16(As + nl*ATOK + c4*4,
                 x + (size_t)(n0g + nl)*DIM_TOTAL + XOFF + kt*(BK*D) + c4*4);
        }
        #pragma unroll
        for (int it = 0; it < B_CH/THREADS; ++it) {
            int idx = tid + it*THREADS;
            int r = idx / (BN/4), c4 = idx - r*(BN/4);
            cp16(Bs + r*BSTR + c4*4,
                 w + woff + (size_t)(kt*BK + r)*MUL + v0 + c4*4);
        }
    };

    float acc[MT][NT][4];
    #pragma unroll
    for (int mt = 0; mt < MT; ++mt)
        #pragma unroll
        for (int nt = 0; nt < NT; ++nt)
            #pragma unroll
            for (int e = 0; e < 4; ++e)
                acc[mt][nt][e] = 0.0f;

    // per-row A offsets (de-interleave hoisted out of the k loop)
    int aOff0[MT], aOff1[MT];
    #pragma unroll
    for (int mt = 0; mt < MT; ++mt) {
        int r0 = wy*WM + mt*16 + g;
        int r1 = r0 + 8;
        aOff0[mt] = (r0/D)*ATOK + (r0 - (r0/D)*D) + q*D;
        aOff1[mt] = (r1/D)*ATOK + (r1 - (r1/D)*D) + q*D;
    }
    int bCol[NT];
    #pragma unroll
    for (int nt = 0; nt < NT; ++nt)
        bCol[nt] = wx*WN + nt*8 + g;

    load_stage(0, sm);
    asm volatile("cp.async.commit_group;" ::: "memory");
    load_stage(1, sm + STAGE_F);
    asm volatile("cp.async.commit_group;" ::: "memory");

    int sidx = 0;
    for (int kt = 0; kt < KT; ++kt) {
        asm volatile("cp.async.wait_group 1;" ::: "memory");
        __syncthreads();
        if (kt + 2 < KT) {
            int ns = sidx + 2; if (ns >= 3) ns -= 3;
            load_stage(kt + 2, sm + ns*STAGE_F);
        }
        asm volatile("cp.async.commit_group;" ::: "memory");

        const float* As = sm + sidx*STAGE_F;
        const float* Bs = As + A_F;
        #pragma unroll
        for (int kk = 0; kk < BK/8; ++kk) {
            uint32_t a[MT][4];
            #pragma unroll
            for (int mt = 0; mt < MT; ++mt) {   // raw fp32: HW truncates to tf32
                a[mt][0] = __float_as_uint(As[aOff0[mt] + (kk*8)*D]);
                a[mt][1] = __float_as_uint(As[aOff1[mt] + (kk*8)*D]);
                a[mt][2] = __float_as_uint(As[aOff0[mt] + (kk*8 + 4)*D]);
                a[mt][3] = __float_as_uint(As[aOff1[mt] + (kk*8 + 4)*D]);
            }
            uint32_t b[NT][2];
            #pragma unroll
            for (int nt = 0; nt < NT; ++nt) {   // weights: rna cvt (unbiased)
                b[nt][0] = f2tf32(Bs[(kk*8 + q    )*BSTR + bCol[nt]]);
                b[nt][1] = f2tf32(Bs[(kk*8 + q + 4)*BSTR + bCol[nt]]);
            }
            #pragma unroll
            for (int mt = 0; mt < MT; ++mt)
                #pragma unroll
                for (int nt = 0; nt < NT; ++nt)
                    asm volatile(
                        "mma.sync.aligned.m16n8k8.row.col.f32.tf32.tf32.f32 "
                        "{%0,%1,%2,%3}, {%4,%5,%6,%7}, {%8,%9}, {%0,%1,%2,%3};"
                        : "+f"(acc[mt][nt][0]), "+f"(acc[mt][nt][1]),
                          "+f"(acc[mt][nt][2]), "+f"(acc[mt][nt][3])
                        : "r"(a[mt][0]), "r"(a[mt][1]), "r"(a[mt][2]), "r"(a[mt][3]),
                          "r"(b[nt][0]), "r"(b[nt][1]));
        }
        ++sidx; if (sidx >= 3) sidx = 0;
    }

    // ---- epilogue: stage C in smem (stages dead), contiguous float4 stores ----
    __syncthreads();
    float (*C)[BN] = reinterpret_cast<float (*)[BN]>(sm);
    #pragma unroll
    for (int mt = 0; mt < MT; ++mt)
        #pragma unroll
        for (int nt = 0; nt < NT; ++nt) {
            int r   = wy*WM + mt*16 + g;
            int col = wx*WN + nt*8 + 2*q;
            C[r    ][col    ] = acc[mt][nt][0];
            C[r    ][col + 1] = acc[mt][nt][1];
            C[r + 8][col    ] = acc[mt][nt][2];
            C[r + 8][col + 1] = acc[mt][nt][3];
        }
    __syncthreads();

    constexpr int TOT4 = BM*BN/4;
    #pragma unroll
    for (int it = 0; it < TOT4/THREADS; ++it) {
        int f    = tid + it*THREADS;
        int base = f*4;
        int nl   = base / (BN*D);
        int j    = base - nl*(BN*D);
        float4 vv;
        vv.x = C[nl*D + (j+0)%D][(j+0)/D] * scale;
        vv.y = C[nl*D + (j+1)%D][(j+1)/D] * scale;
        vv.z = C[nl*D + (j+2)%D][(j+2)/D] * scale;
        vv.w = C[nl*D + (j+3)%D][(j+3)/D] * scale;
        *reinterpret_cast<float4*>(
            out + (size_t)(n0g + nl)*DIM_TOTAL + XOFF + v0*D + j) = vv;
    }
}

extern "C" void kernel_launch(void* const* d_in, const int* in_sizes, int n_in,
                              void* d_out, int out_size)
{
    const float* x   = (const float*)d_in[0];
    const float* w   = (const float*)d_in[1];
    float*       out = (float*)d_out;
    (void)in_sizes; (void)n_in; (void)out_size;

    // seg0: D=1, MUL=512. Tile 128x128x32, 4 warps of 64x64 (MT=4, NT=8).
    {
        auto kfn = seg_linear_tc<1,128,128,32,64,64,0,512>;
        constexpr int STAGE_B = (128*(32+4) + 32*(128+8))*4;   // 35840
        constexpr int SMEM = (3*STAGE_B > 128*128*4) ? 3*STAGE_B : 128*128*4; // 107520
        cudaFuncSetAttribute(kfn, cudaFuncAttributeMaxDynamicSharedMemorySize, SMEM);
        dim3 grid(16384/128, 512/128);
        kfn<<<grid, 128, SMEM>>>(x, w, out, 0, 0.044194173824159216f);
    }
    // seg1: D=3, MUL=256. Tile 96x128x32, 4 warps of 48x64 (MT=3, NT=8).
    {
        auto kfn = seg_linear_tc<3,96,128,32,48,64,512,256>;
        constexpr int STAGE_B = (32*(96+4) + 32*(128+8))*4;    // 30208
        constexpr int SMEM = (3*STAGE_B > 96*128*4) ? 3*STAGE_B : 96*128*4;   // 90624
        cudaFuncSetAttribute(kfn, cudaFuncAttributeMaxDynamicSharedMemorySize, SMEM);
        dim3 grid(49152/96, 256/128);
        kfn<<<grid, 128, SMEM>>>(x, w, out, 512*512, 0.0625f);
    }
    // seg2: D=5, MUL=128. Tile 160x128x16, 4 warps of 80x64 (MT=5, NT=8).
    {
        auto kfn = seg_linear_tc<5,160,128,16,80,64,1280,128>;
        constexpr int STAGE_B = (32*(80+4) + 16*(128+8))*4;    // 19456
        constexpr int SMEM = (3*STAGE_B > 160*128*4) ? 3*STAGE_B : 160*128*4; // 81920
        cudaFuncSetAttribute(kfn, cudaFuncAttributeMaxDynamicSharedMemorySize, SMEM);
        dim3 grid(81920/160, 128/128);
        kfn<<<grid, 128, SMEM>>>(x, w, out, 512*512 + 256*256, 0.08838834764831843f);
    }
}